// round 12
// baseline (speedup 1.0000x reference)
#include <cuda_runtime.h>
#include <cstdint>

// Problem dims (fixed for this dataset)
#define NTOK    8192          // B*T
#define GDIM    32            // algebra dim
#define INO     128
#define OUTO    128
#define DMODEL  4096          // GDIM*INO
#define CHUNK   2048          // tokens per pipeline chunk (scratch stays L2-resident)
#define NCHUNK  4
#define WELEMS  (GDIM*OUTO*INO)   // 524288

// -------- scratch (device globals; no allocation allowed) --------
__device__ float g_xm[GDIM * CHUNK * INO];    // 32 MB  xm[h][tloc][i]  (tf32-rounded)
__device__ float g_yp[GDIM * CHUNK * OUTO];   // 32 MB  yp[h][tloc][o]
__device__ float g_wq[WELEMS];                // 2 MB   ternary weights in {-1,0,1}
__device__ float g_partial[256];
__device__ float g_scale;

// ======================= K0: weight quantization ========================
__global__ void k0a_abssum(const float* __restrict__ w) {
    __shared__ float sm[256];
    int tid = threadIdx.x;
    const float4* w4 = (const float4*)w;
    int base = (blockIdx.x * 256 + tid) * 2;           // 2 float4 = 8 elems/thread
    float4 p = w4[base];
    float4 q = w4[base + 1];
    float s = fabsf(p.x) + fabsf(p.y) + fabsf(p.z) + fabsf(p.w)
            + fabsf(q.x) + fabsf(q.y) + fabsf(q.z) + fabsf(q.w);
    sm[tid] = s;
    __syncthreads();
    for (int st = 128; st > 0; st >>= 1) {
        if (tid < st) sm[tid] += sm[tid + st];
        __syncthreads();
    }
    if (tid == 0) g_partial[blockIdx.x] = sm[0];
}

__global__ void k0b_finish() {
    __shared__ float sm[256];
    int tid = threadIdx.x;
    sm[tid] = g_partial[tid];
    __syncthreads();
    for (int st = 128; st > 0; st >>= 1) {
        if (tid < st) sm[tid] += sm[tid + st];
        __syncthreads();
    }
    if (tid == 0) g_scale = sm[0] / (float)WELEMS + 1e-8f;
}

__global__ void k0c_quant(const float* __restrict__ w) {
    int i = blockIdx.x * blockDim.x + threadIdx.x;
    if (i < WELEMS) {
        float s = g_scale;
        // match jnp: round(w/scale) with IEEE divide + round-half-even, clip to [-1,1]
        float q = rintf(__fdiv_rn(w[i], s));
        q = fminf(1.0f, fmaxf(-1.0f, q));
        g_wq[i] = q;   // ternary {-1,0,1}; scale deferred to K3 epilogue
    }
}

// ======================= K1: alpha * x, FHT over g, -> tf32 =============
__global__ void k1_fht_in(const float* __restrict__ x,
                          const float* __restrict__ alpha,
                          int tok0) {
    int i    = threadIdx.x;                              // 0..127 (in_o)
    int tloc = blockIdx.x * blockDim.y + threadIdx.y;    // token within chunk
    const float* xt = x + (size_t)(tok0 + tloc) * DMODEL;

    float v[GDIM];
#pragma unroll
    for (int g = 0; g < GDIM; g++)
        v[g] = xt[g * INO + i] * alpha[g * INO + i];

    // unnormalized 32-pt Walsh-Hadamard (Sylvester): out[h] = sum_g (-1)^popc(g&h) in[g]
#pragma unroll
    for (int s = 1; s < GDIM; s <<= 1) {
#pragma unroll
        for (int j = 0; j < GDIM; j++) {
            if (!(j & s)) {
                float a = v[j], b = v[j | s];
                v[j]     = a + b;
                v[j | s] = a - b;
            }
        }
    }

#pragma unroll
    for (int h = 0; h < GDIM; h++) {
        uint32_t t;
        asm("cvt.rna.tf32.f32 %0, %1;" : "=r"(t) : "f"(v[h]));
        g_xm[((size_t)h * CHUNK + tloc) * INO + i] = __uint_as_float(t);
    }
}

// ======================= K2: grouped GEMM (tf32 mma.sync) ================
// Per h: yp[t,o] = sum_i xm[t,i] * wq[h,o,i].  CTA tile 128x128, K=128.
__device__ __forceinline__ void mma_tf32(float c[4], const uint32_t a[4], const uint32_t b[2]) {
    asm volatile(
        "mma.sync.aligned.m16n8k8.row.col.f32.tf32.tf32.f32 "
        "{%0,%1,%2,%3}, {%4,%5,%6,%7}, {%8,%9}, {%0,%1,%2,%3};"
        : "+f"(c[0]), "+f"(c[1]), "+f"(c[2]), "+f"(c[3])
        : "r"(a[0]), "r"(a[1]), "r"(a[2]), "r"(a[3]),
          "r"(b[0]), "r"(b[1]));
}

__global__ void __launch_bounds__(256) k2_gemm() {
    __shared__ float As[128][36];   // [token][k], padded: conflict-free, float4-aligned
    __shared__ float Bs[128][36];   // [out  ][k]

    const int h    = blockIdx.y;
    const int tile = blockIdx.x;
    const int tid  = threadIdx.x;
    const int warp = tid >> 5;
    const int lane = tid & 31;
    const int wm = (warp & 3) * 32;    // 4 warps along M (32 rows each)
    const int wn = (warp >> 2) * 64;   // 2 warps along N (64 cols each)
    const int r = lane >> 2;           // 0..7
    const int c = lane & 3;            // 0..3

    const float* Ag = g_xm + ((size_t)h * CHUNK + (size_t)tile * 128) * INO;
    const float* Bg = g_wq + (size_t)h * (OUTO * INO);

    float acc[2][8][4];
#pragma unroll
    for (int mi = 0; mi < 2; mi++)
#pragma unroll
        for (int ni = 0; ni < 8; ni++)
#pragma unroll
            for (int e = 0; e < 4; e++) acc[mi][ni][e] = 0.0f;

#pragma unroll 1
    for (int kc = 0; kc < 4; kc++) {      // K chunks of 32
        // cooperative load: 128 rows x 32 cols = 1024 float4, 256 threads x 4
#pragma unroll
        for (int j = 0; j < 4; j++) {
            int id  = tid + j * 256;
            int row = id >> 3;
            int c4  = (id & 7) * 4;
            float4 va = *(const float4*)(Ag + row * INO + kc * 32 + c4);
            *(float4*)(&As[row][c4]) = va;
            float4 vb = *(const float4*)(Bg + row * INO + kc * 32 + c4);
            *(float4*)(&Bs[row][c4]) = vb;
        }
        __syncthreads();

#pragma unroll
        for (int ks = 0; ks < 4; ks++) {  // k-steps of 8
            const int k0 = ks * 8;
            uint32_t a[2][4];
#pragma unroll
            for (int mi = 0; mi < 2; mi++) {
                int rr = wm + mi * 16 + r;
                a[mi][0] = __float_as_uint(As[rr][k0 + c]);
                a[mi][1] = __float_as_uint(As[rr + 8][k0 + c]);
                a[mi][2] = __float_as_uint(As[rr][k0 + c + 4]);
                a[mi][3] = __float_as_uint(As[rr + 8][k0 + c + 4]);
            }
#pragma unroll
            for (int ni = 0; ni < 8; ni++) {
                uint32_t b[2];
                int oo = wn + ni * 8 + r;
                b[0] = __float_as_uint(Bs[oo][k0 + c]);
                b[1] = __float_as_uint(Bs[oo][k0 + c + 4]);
                mma_tf32(acc[0][ni], a[0], b);
                mma_tf32(acc[1][ni], a[1], b);
            }
        }
        __syncthreads();
    }

    // epilogue: yp[h][t][o]
    float* Yg = g_yp + ((size_t)h * CHUNK + (size_t)tile * 128) * OUTO;
#pragma unroll
    for (int mi = 0; mi < 2; mi++) {
#pragma unroll
        for (int ni = 0; ni < 8; ni++) {
            int row0 = wm + mi * 16 + r;
            int col  = wn + ni * 8 + c * 2;
            *(float2*)(Yg + (size_t)row0 * OUTO + col) =
                make_float2(acc[mi][ni][0], acc[mi][ni][1]);
            *(float2*)(Yg + (size_t)(row0 + 8) * OUTO + col) =
                make_float2(acc[mi][ni][2], acc[mi][ni][3]);
        }
    }
}

// ======================= K3: FHT over h, * beta * scale/32 ==============
__global__ void k3_fht_out(const float* __restrict__ beta,
                           float* __restrict__ y,
                           int tok0) {
    int o    = threadIdx.x;                              // 0..127 (out_o)
    int tloc = blockIdx.x * blockDim.y + threadIdx.y;

    float v[GDIM];
#pragma unroll
    for (int h = 0; h < GDIM; h++)
        v[h] = g_yp[((size_t)h * CHUNK + tloc) * OUTO + o];

#pragma unroll
    for (int s = 1; s < GDIM; s <<= 1) {
#pragma unroll
        for (int j = 0; j < GDIM; j++) {
            if (!(j & s)) {
                float a = v[j], b = v[j | s];
                v[j]     = a + b;
                v[j | s] = a - b;
            }
        }
    }

    const float fac = g_scale * (1.0f / 32.0f);   // deferred w-scale and two 1/sqrt(32)
    float* yt = y + (size_t)(tok0 + tloc) * DMODEL;
#pragma unroll
    for (int g = 0; g < GDIM; g++)
        yt[g * OUTO + o] = v[g] * (beta[g * OUTO + o] * fac);
}

// ======================= launch ==========================================
extern "C" void kernel_launch(void* const* d_in, const int* in_sizes, int n_in,
                              void* d_out, int out_size) {
    const float* x     = (const float*)d_in[0];   // [8192, 4096]
    const float* w     = (const float*)d_in[1];   // [32, 128, 128]
    const float* alpha = (const float*)d_in[2];   // [32, 128]
    const float* beta  = (const float*)d_in[3];   // [32, 128]
    float* y = (float*)d_out;

    // weight quantization (chunk-independent)
    k0a_abssum<<<256, 256>>>(w);
    k0b_finish<<<1, 256>>>();
    k0c_quant<<<1024, 512>>>(w);

    // pipelined chunks; same stream => serialized, scratch stays L2-hot
    for (int ck = 0; ck < NCHUNK; ck++) {
        int tok0 = ck * CHUNK;
        k1_fht_in<<<dim3(CHUNK / 2), dim3(128, 2)>>>(x, alpha, tok0);
        k2_gemm<<<dim3(CHUNK / 128, GDIM), 256>>>();
        k3_fht_out<<<dim3(CHUNK / 2), dim3(128, 2)>>>(beta, y, tok0);
    }
}

// round 13
// speedup vs baseline: 1.0116x; 1.0116x over previous
#include <cuda_runtime.h>
#include <cstdint>

// Problem dims (fixed for this dataset)
#define NTOK    8192          // B*T
#define GDIM    32            // algebra dim
#define INO     128
#define OUTO    128
#define DMODEL  4096          // GDIM*INO
#define CHUNK   2048          // tokens per pipeline chunk (scratch stays L2-resident)
#define NCHUNK  4
#define WELEMS  (GDIM*OUTO*INO)   // 524288

// -------- scratch (device globals; no allocation allowed) --------
__device__ float g_xm[GDIM * CHUNK * INO];    // 32 MB  xm[h][tloc][i]  (tf32-rounded)
__device__ float g_yp[GDIM * CHUNK * OUTO];   // 32 MB  yp[h][tloc][o]
__device__ float g_wq[WELEMS];                // 2 MB   ternary weights in {-1,0,1}
__device__ float g_partial[256];
__device__ float g_scale;

// ======================= K0: weight quantization ========================
__global__ void k0a_abssum(const float* __restrict__ w) {
    __shared__ float sm[256];
    int tid = threadIdx.x;
    const float4* w4 = (const float4*)w;
    int base = (blockIdx.x * 256 + tid) * 2;           // 2 float4 = 8 elems/thread
    float4 p = w4[base];
    float4 q = w4[base + 1];
    float s = fabsf(p.x) + fabsf(p.y) + fabsf(p.z) + fabsf(p.w)
            + fabsf(q.x) + fabsf(q.y) + fabsf(q.z) + fabsf(q.w);
    sm[tid] = s;
    __syncthreads();
    for (int st = 128; st > 0; st >>= 1) {
        if (tid < st) sm[tid] += sm[tid + st];
        __syncthreads();
    }
    if (tid == 0) g_partial[blockIdx.x] = sm[0];
}

__global__ void k0b_finish() {
    __shared__ float sm[256];
    int tid = threadIdx.x;
    sm[tid] = g_partial[tid];
    __syncthreads();
    for (int st = 128; st > 0; st >>= 1) {
        if (tid < st) sm[tid] += sm[tid + st];
        __syncthreads();
    }
    if (tid == 0) g_scale = sm[0] / (float)WELEMS + 1e-8f;
}

__global__ void k0c_quant(const float* __restrict__ w) {
    int i = blockIdx.x * blockDim.x + threadIdx.x;
    if (i < WELEMS) {
        float s = g_scale;
        // match jnp: round(w/scale) with IEEE divide + round-half-even, clip to [-1,1]
        float q = rintf(__fdiv_rn(w[i], s));
        q = fminf(1.0f, fmaxf(-1.0f, q));
        g_wq[i] = q;   // ternary {-1,0,1}; scale deferred to K3 epilogue
    }
}

// ======================= K1: alpha * x, FHT over g, -> tf32 =============
__global__ void k1_fht_in(const float* __restrict__ x,
                          const float* __restrict__ alpha,
                          int tok0) {
    int i    = threadIdx.x;                              // 0..127 (in_o)
    int tloc = blockIdx.x * blockDim.y + threadIdx.y;    // token within chunk
    const float* xt = x + (size_t)(tok0 + tloc) * DMODEL;

    float v[GDIM];
#pragma unroll
    for (int g = 0; g < GDIM; g++)
        v[g] = xt[g * INO + i] * alpha[g * INO + i];

    // unnormalized 32-pt Walsh-Hadamard (Sylvester): out[h] = sum_g (-1)^popc(g&h) in[g]
#pragma unroll
    for (int s = 1; s < GDIM; s <<= 1) {
#pragma unroll
        for (int j = 0; j < GDIM; j++) {
            if (!(j & s)) {
                float a = v[j], b = v[j | s];
                v[j]     = a + b;
                v[j | s] = a - b;
            }
        }
    }

#pragma unroll
    for (int h = 0; h < GDIM; h++) {
        uint32_t t;
        asm("cvt.rna.tf32.f32 %0, %1;" : "=r"(t) : "f"(v[h]));
        g_xm[((size_t)h * CHUNK + tloc) * INO + i] = __uint_as_float(t);
    }
}

// ======================= K2: grouped GEMM (tf32 mma.sync) ================
// Per h: yp[t,o] = sum_i xm[t,i] * wq[h,o,i].  CTA tile 128x128, K=128.
__device__ __forceinline__ void mma_tf32(float c[4], const uint32_t a[4], const uint32_t b[2]) {
    asm volatile(
        "mma.sync.aligned.m16n8k8.row.col.f32.tf32.tf32.f32 "
        "{%0,%1,%2,%3}, {%4,%5,%6,%7}, {%8,%9}, {%0,%1,%2,%3};"
        : "+f"(c[0]), "+f"(c[1]), "+f"(c[2]), "+f"(c[3])
        : "r"(a[0]), "r"(a[1]), "r"(a[2]), "r"(a[3]),
          "r"(b[0]), "r"(b[1]));
}

__global__ void __launch_bounds__(256) k2_gemm() {
    __shared__ float As[128][36];   // [token][k], padded: conflict-free, float4-aligned
    __shared__ float Bs[128][36];   // [out  ][k]

    const int h    = blockIdx.y;
    const int tile = blockIdx.x;
    const int tid  = threadIdx.x;
    const int warp = tid >> 5;
    const int lane = tid & 31;
    const int wm = (warp & 3) * 32;    // 4 warps along M (32 rows each)
    const int wn = (warp >> 2) * 64;   // 2 warps along N (64 cols each)
    const int r = lane >> 2;           // 0..7
    const int c = lane & 3;            // 0..3

    const float* Ag = g_xm + ((size_t)h * CHUNK + (size_t)tile * 128) * INO;
    const float* Bg = g_wq + (size_t)h * (OUTO * INO);

    float acc[2][8][4];
#pragma unroll
    for (int mi = 0; mi < 2; mi++)
#pragma unroll
        for (int ni = 0; ni < 8; ni++)
#pragma unroll
            for (int e = 0; e < 4; e++) acc[mi][ni][e] = 0.0f;

#pragma unroll 1
    for (int kc = 0; kc < 4; kc++) {      // K chunks of 32
        // cooperative load: 128 rows x 32 cols = 1024 float4, 256 threads x 4
#pragma unroll
        for (int j = 0; j < 4; j++) {
            int id  = tid + j * 256;
            int row = id >> 3;
            int c4  = (id & 7) * 4;
            float4 va = *(const float4*)(Ag + row * INO + kc * 32 + c4);
            *(float4*)(&As[row][c4]) = va;
            float4 vb = *(const float4*)(Bg + row * INO + kc * 32 + c4);
            *(float4*)(&Bs[row][c4]) = vb;
        }
        __syncthreads();

#pragma unroll
        for (int ks = 0; ks < 4; ks++) {  // k-steps of 8
            const int k0 = ks * 8;
            uint32_t a[2][4];
#pragma unroll
            for (int mi = 0; mi < 2; mi++) {
                int rr = wm + mi * 16 + r;
                a[mi][0] = __float_as_uint(As[rr][k0 + c]);
                a[mi][1] = __float_as_uint(As[rr + 8][k0 + c]);
                a[mi][2] = __float_as_uint(As[rr][k0 + c + 4]);
                a[mi][3] = __float_as_uint(As[rr + 8][k0 + c + 4]);
            }
#pragma unroll
            for (int ni = 0; ni < 8; ni++) {
                uint32_t b[2];
                int oo = wn + ni * 8 + r;
                b[0] = __float_as_uint(Bs[oo][k0 + c]);
                b[1] = __float_as_uint(Bs[oo][k0 + c + 4]);
                mma_tf32(acc[0][ni], a[0], b);
                mma_tf32(acc[1][ni], a[1], b);
            }
        }
        __syncthreads();
    }

    // epilogue: yp[h][t][o]
    float* Yg = g_yp + ((size_t)h * CHUNK + (size_t)tile * 128) * OUTO;
#pragma unroll
    for (int mi = 0; mi < 2; mi++) {
#pragma unroll
        for (int ni = 0; ni < 8; ni++) {
            int row0 = wm + mi * 16 + r;
            int col  = wn + ni * 8 + c * 2;
            *(float2*)(Yg + (size_t)row0 * OUTO + col) =
                make_float2(acc[mi][ni][0], acc[mi][ni][1]);
            *(float2*)(Yg + (size_t)(row0 + 8) * OUTO + col) =
                make_float2(acc[mi][ni][2], acc[mi][ni][3]);
        }
    }
}

// ======================= K3: FHT over h, * beta * scale/32 ==============
__global__ void k3_fht_out(const float* __restrict__ beta,
                           float* __restrict__ y,
                           int tok0) {
    int o    = threadIdx.x;                              // 0..127 (out_o)
    int tloc = blockIdx.x * blockDim.y + threadIdx.y;

    float v[GDIM];
#pragma unroll
    for (int h = 0; h < GDIM; h++)
        v[h] = g_yp[((size_t)h * CHUNK + tloc) * OUTO + o];

#pragma unroll
    for (int s = 1; s < GDIM; s <<= 1) {
#pragma unroll
        for (int j = 0; j < GDIM; j++) {
            if (!(j & s)) {
                float a = v[j], b = v[j | s];
                v[j]     = a + b;
                v[j | s] = a - b;
            }
        }
    }

    const float fac = g_scale * (1.0f / 32.0f);   // deferred w-scale and two 1/sqrt(32)
    float* yt = y + (size_t)(tok0 + tloc) * DMODEL;
#pragma unroll
    for (int g = 0; g < GDIM; g++)
        yt[g * OUTO + o] = v[g] * (beta[g * OUTO + o] * fac);
}

// ======================= launch ==========================================
extern "C" void kernel_launch(void* const* d_in, const int* in_sizes, int n_in,
                              void* d_out, int out_size) {
    const float* x     = (const float*)d_in[0];   // [8192, 4096]
    const float* w     = (const float*)d_in[1];   // [32, 128, 128]
    const float* alpha = (const float*)d_in[2];   // [32, 128]
    const float* beta  = (const float*)d_in[3];   // [32, 128]
    float* y = (float*)d_out;

    // weight quantization (chunk-independent)
    k0a_abssum<<<256, 256>>>(w);
    k0b_finish<<<1, 256>>>();
    k0c_quant<<<1024, 512>>>(w);

    // pipelined chunks; same stream => serialized, scratch stays L2-hot
    for (int ck = 0; ck < NCHUNK; ck++) {
        int tok0 = ck * CHUNK;
        k1_fht_in<<<dim3(CHUNK / 2), dim3(128, 2)>>>(x, alpha, tok0);
        k2_gemm<<<dim3(CHUNK / 128, GDIM), 256>>>();
        k3_fht_out<<<dim3(CHUNK / 2), dim3(128, 2)>>>(beta, y, tok0);
    }
}